// round 1
// baseline (speedup 1.0000x reference)
#include <cuda_runtime.h>
#include <math.h>

// Scratch (no cudaMalloc allowed): T[o][kh][wi] and flattened se_w.
__device__ float g_T[10 * 64 * 120];   // 76800 floats
__device__ float g_sew[128];           // se_w flattened (2 x 64)

#define T_BLOCKS 40
#define T_THREADS 256
#define T_TOTAL (10 * 64 * 120)

// Kernel A: blocks 0..39 compute T (independent of SE weights).
// Block 40 computes se_w (norms -> correlations -> 2x GEMV -> sigmoid -> softmax).
__global__ void cnn_kA(const float* __restrict__ x,
                       const float* __restrict__ se_w1,
                       const float* __restrict__ se_b1,
                       const float* __restrict__ se_w2,
                       const float* __restrict__ se_b2,
                       const float* __restrict__ conv_w) {
    if (blockIdx.x < T_BLOCKS) {
        int tid = blockIdx.x * T_THREADS + threadIdx.x;   // 0..10239
        for (int idx = tid; idx < T_TOTAL; idx += T_BLOCKS * T_THREADS) {
            int wi = idx % 120;
            int r  = idx / 120;          // r = o*64 + kh
            int kh = r & 63;
            const float* e = x + (kh + 1) * 128 + wi;     // eeg[kh][wi..wi+8]
            const float* w = conv_w + r * 9;
            float s = 0.f;
#pragma unroll
            for (int kw = 0; kw < 9; kw++) s = fmaf(e[kw], w[kw], s);
            g_T[idx] = s;
        }
        return;
    }

    // ---- SE-weight block (uses 128 of 256 threads) ----
    __shared__ float norme[64];
    __shared__ float scal[4];       // dot0a, dot0b, ||wav_a||, ||wav_b||
    __shared__ float eegr[2][64];
    __shared__ float hsh[2][64];
    __shared__ float ssh[2][64];
    int t = threadIdx.x;

    if (t < 64) {
        const float* e = x + (t + 1) * 128;
        float a = 0.f;
        for (int i = 0; i < 128; i++) a = fmaf(e[i], e[i], a);
        norme[t] = sqrtf(a);
    } else if (t < 68) {
        int which = t - 64;
        const float* e0 = x + 128;                 // eeg channel 0
        const float* wv = (which & 1) ? (x + 65 * 128) : x;
        float a = 0.f;
        if (which < 2) {
            for (int i = 0; i < 128; i++) a = fmaf(e0[i], wv[i], a);
        } else {
            for (int i = 0; i < 128; i++) a = fmaf(wv[i], wv[i], a);
            a = sqrtf(a);
        }
        scal[which] = a;
    }
    __syncthreads();

    if (t < 128) {
        // Reference quirk: numerator is channel-0's dot only (jnp.diagonal of (64,1)).
        int r = t >> 6, j = t & 63;
        float num = scal[r];          // dot0a or dot0b
        float nw  = scal[2 + r];      // ||wav_a|| or ||wav_b||
        eegr[r][j] = num / (norme[j] * nw);
    }
    __syncthreads();

    if (t < 128) {
        int r = t >> 6, j = t & 63;
        float a = se_b1[j];
        const float* w = se_w1 + j * 64;
        for (int i = 0; i < 64; i++) a = fmaf(eegr[r][i], w[i], a);
        hsh[r][j] = tanhf(a);
    }
    __syncthreads();

    if (t < 128) {
        int r = t >> 6, j = t & 63;
        float a = se_b2[j];
        const float* w = se_w2 + j * 64;
        for (int i = 0; i < 64; i++) a = fmaf(hsh[r][i], w[i], a);
        ssh[r][j] = 1.f / (1.f + expf(-a));
    }
    __syncthreads();

    if (t < 2) {   // row-wise softmax over 64, serial (trivial)
        float m = -1e30f;
        for (int j = 0; j < 64; j++) m = fmaxf(m, ssh[t][j]);
        float sum = 0.f;
        float tmp[64];
        for (int j = 0; j < 64; j++) { tmp[j] = expf(ssh[t][j] - m); sum += tmp[j]; }
        float inv = 1.f / sum;
        for (int j = 0; j < 64; j++) g_sew[t * 64 + j] = tmp[j] * inv;
    }
}

// Kernel B: combine conv = sum_kh se_w[hi][kh] * T[o][kh][wi] + bias,
// relu, mean over wi, then the FCN tail + softmax. One block.
__global__ void cnn_kB(const float* __restrict__ conv_b,
                       const float* __restrict__ fcn_w1,
                       const float* __restrict__ fcn_b1,
                       const float* __restrict__ fcn_w2,
                       const float* __restrict__ fcn_b2,
                       float* __restrict__ out) {
    __shared__ float sacc[20];
    __shared__ float sew[128];
    int t = threadIdx.x;
    if (t < 20) sacc[t] = 0.f;
    if (t < 128) sew[t] = g_sew[t];
    __syncthreads();

    // 2400 conv outputs: idx = (o*2+hi)*120 + wi
    for (int idx = t; idx < 2400; idx += blockDim.x) {
        int wi = idx % 120;
        int p  = idx / 120;        // o*2 + hi
        int hi = p & 1, o = p >> 1;
        float a = conv_b[o];
        const float* Trow = g_T + (o * 64) * 120 + wi;
        const float* w = sew + hi * 64;
#pragma unroll 8
        for (int kh = 0; kh < 64; kh++)
            a = fmaf(w[kh], Trow[kh * 120], a);
        atomicAdd(&sacc[p], fmaxf(a, 0.f));
    }
    __syncthreads();

    if (t == 0) {
        float y[20];
        for (int k = 0; k < 20; k++) y[k] = sacc[k] * (1.f / 120.f);
        float h2[10];
        for (int j = 0; j < 10; j++) {
            float a = fcn_b1[j];
            const float* w = fcn_w1 + j * 20;
            for (int k = 0; k < 20; k++) a = fmaf(y[k], w[k], a);
            h2[j] = 1.f / (1.f + expf(-a));
        }
        float l0 = fcn_b2[0], l1 = fcn_b2[1];
        for (int j = 0; j < 10; j++) {
            l0 = fmaf(h2[j], fcn_w2[j], l0);
            l1 = fmaf(h2[j], fcn_w2[10 + j], l1);
        }
        float m = fmaxf(l0, l1);
        float e0 = expf(l0 - m), e1 = expf(l1 - m);
        float inv = 1.f / (e0 + e1);
        out[0] = e0 * inv;
        out[1] = e1 * inv;
    }
}

extern "C" void kernel_launch(void* const* d_in, const int* in_sizes, int n_in,
                              void* d_out, int out_size) {
    const float* x      = (const float*)d_in[0];
    const float* se_w1  = (const float*)d_in[1];
    const float* se_b1  = (const float*)d_in[2];
    const float* se_w2  = (const float*)d_in[3];
    const float* se_b2  = (const float*)d_in[4];
    const float* conv_w = (const float*)d_in[5];
    const float* conv_b = (const float*)d_in[6];
    const float* fcn_w1 = (const float*)d_in[7];
    const float* fcn_b1 = (const float*)d_in[8];
    const float* fcn_w2 = (const float*)d_in[9];
    const float* fcn_b2 = (const float*)d_in[10];
    float* out = (float*)d_out;

    cnn_kA<<<T_BLOCKS + 1, T_THREADS>>>(x, se_w1, se_b1, se_w2, se_b2, conv_w);
    cnn_kB<<<1, 256>>>(conv_b, fcn_w1, fcn_b1, fcn_w2, fcn_b2, out);
}

// round 2
// speedup vs baseline: 2.0442x; 2.0442x over previous
#include <cuda_runtime.h>
#include <math.h>

// Scratch (no cudaMalloc allowed)
__device__ float g_T[10 * 64 * 120];   // T[o][kh][wi]
__device__ float g_sew[128];           // se_w flattened (2 x 64)
__device__ float g_mean[20];           // per-(o,hi) relu-mean
__device__ unsigned g_count = 0;       // grid barrier arrivals (self-resetting)
__device__ unsigned g_sense = 0;       // grid barrier generation (monotonic)

#define NB 32
#define NT 256
#define T_TOTAL (10 * 64 * 120)

// Sense-based grid barrier. All NB blocks co-resident (NB << 148 SMs).
// s0 = g_sense sampled at kernel entry (per launch); k = barrier index (1,2,...).
__device__ __forceinline__ void grid_barrier(unsigned s0, unsigned k) {
    __syncthreads();
    if (threadIdx.x == 0) {
        __threadfence();
        unsigned old = atomicAdd(&g_count, 1u);
        if (old == NB - 1) {
            g_count = 0;
            __threadfence();
            atomicAdd(&g_sense, 1u);
        } else {
            while ((int)(*(volatile unsigned*)&g_sense - (s0 + k)) < 0) {
                __nanosleep(32);
            }
        }
    }
    __syncthreads();
}

__global__ void __launch_bounds__(NT, 1)
cnn_fused(const float* __restrict__ x,
          const float* __restrict__ se_w1,
          const float* __restrict__ se_b1,
          const float* __restrict__ se_w2,
          const float* __restrict__ se_b2,
          const float* __restrict__ conv_w,
          const float* __restrict__ conv_b,
          const float* __restrict__ fcn_w1,
          const float* __restrict__ fcn_b1,
          const float* __restrict__ fcn_w2,
          const float* __restrict__ fcn_b2,
          float* __restrict__ out) {
    const int t = threadIdx.x;
    const int b = blockIdx.x;

    __shared__ float smem[256];        // reductions / ws / tail scratch
    __shared__ float norme[64];
    __shared__ float scal[4];
    __shared__ float eegr[2][64];
    __shared__ float hsh[2][64];
    __shared__ float ssh[2][64];

    unsigned s0 = 0;
    if (t == 0) s0 = *(volatile unsigned*)&g_sense;

    // ================= Phase 1 =================
    if (b < NB - 1) {
        // Blocks 0..30: T[o][kh][wi] = sum_kw eeg[kh][wi+kw] * conv_w[o,kh,kw]
        int tid = b * NT + t;                       // 0..7935
        for (int idx = tid; idx < T_TOTAL; idx += (NB - 1) * NT) {
            int wi = idx % 120;
            int r  = idx / 120;                     // r = o*64 + kh
            int kh = r & 63;
            const float* e = x + (kh + 1) * 128 + wi;
            const float* w = conv_w + r * 9;
            float s = 0.f;
#pragma unroll
            for (int kw = 0; kw < 9; kw++) s = fmaf(e[kw], w[kw], s);
            g_T[idx] = s;
        }
    } else {
        // Block 31: SE weights
        if (t < 64) {
            const float* e = x + (t + 1) * 128;
            float a = 0.f;
            for (int i = 0; i < 128; i++) a = fmaf(e[i], e[i], a);
            norme[t] = sqrtf(a);
        } else if (t < 68) {
            int which = t - 64;
            const float* e0 = x + 128;              // eeg channel 0
            const float* wv = (which & 1) ? (x + 65 * 128) : x;
            float a = 0.f;
            if (which < 2) {
                for (int i = 0; i < 128; i++) a = fmaf(e0[i], wv[i], a);
            } else {
                for (int i = 0; i < 128; i++) a = fmaf(wv[i], wv[i], a);
                a = sqrtf(a);
            }
            scal[which] = a;
        }
        __syncthreads();

        if (t < 128) {
            // Reference quirk: numerator = channel-0 dot only (jnp.diagonal of (64,1))
            int r = t >> 6, j = t & 63;
            eegr[r][j] = scal[r] / (norme[j] * scal[2 + r]);
        }
        __syncthreads();

        if (t < 128) {
            int r = t >> 6, j = t & 63;
            float a = se_b1[j];
            const float* w = se_w1 + j * 64;
#pragma unroll 8
            for (int i = 0; i < 64; i++) a = fmaf(eegr[r][i], w[i], a);
            hsh[r][j] = tanhf(a);
        }
        __syncthreads();

        if (t < 128) {
            int r = t >> 6, j = t & 63;
            float a = se_b2[j];
            const float* w = se_w2 + j * 64;
#pragma unroll 8
            for (int i = 0; i < 64; i++) a = fmaf(hsh[r][i], w[i], a);
            ssh[r][j] = 1.f / (1.f + expf(-a));
        }
        __syncthreads();

        // Row-wise softmax over 64 (rows r=0,1), tree reductions in shared.
        // max reduce
        smem[t] = (t < 128) ? ssh[t >> 6][t & 63] : -1e30f;
        __syncthreads();
#pragma unroll
        for (int s = 32; s >= 1; s >>= 1) {
            if (t < 128 && (t & 63) < s) {
                float o_ = smem[t + s];
                if (o_ > smem[t]) smem[t] = o_;
            }
            __syncthreads();
        }
        float rowmax = (t < 128) ? smem[(t >> 6) << 6] : 0.f;
        __syncthreads();
        float ex = (t < 128) ? expf(ssh[t >> 6][t & 63] - rowmax) : 0.f;
        smem[t] = (t < 128) ? ex : 0.f;
        __syncthreads();
#pragma unroll
        for (int s = 32; s >= 1; s >>= 1) {
            if (t < 128 && (t & 63) < s) smem[t] += smem[t + s];
            __syncthreads();
        }
        if (t < 128) g_sew[t] = ex / smem[(t >> 6) << 6];
    }

    grid_barrier(s0, 1);

    // ================= Phase 2: combine + relu + mean =================
    if (b < 20) {
        int o = b >> 1, hi = b & 1;
        __shared__ float ws[64];
        if (t < 64) ws[t] = g_sew[hi * 64 + t];
        __syncthreads();

        float val = 0.f;
        if (t < 120) {
            const float* Trow = g_T + (o * 64) * 120 + t;
            float a0 = 0.f, a1 = 0.f, a2 = 0.f, a3 = 0.f;
#pragma unroll
            for (int kh = 0; kh < 64; kh += 4) {
                a0 = fmaf(ws[kh + 0], Trow[(kh + 0) * 120], a0);
                a1 = fmaf(ws[kh + 1], Trow[(kh + 1) * 120], a1);
                a2 = fmaf(ws[kh + 2], Trow[(kh + 2) * 120], a2);
                a3 = fmaf(ws[kh + 3], Trow[(kh + 3) * 120], a3);
            }
            float a = conv_b[o] + ((a0 + a1) + (a2 + a3));
            val = fmaxf(a, 0.f);
        }
        smem[t] = val;
        __syncthreads();
#pragma unroll
        for (int s = 128; s >= 1; s >>= 1) {
            if (t < s) smem[t] += smem[t + s];
            __syncthreads();
        }
        if (t == 0) g_mean[b] = smem[0] * (1.f / 120.f);
    }

    grid_barrier(s0, 2);

    // ================= Phase 3: FCN tail (block 0) =================
    if (b == 0) {
        __shared__ float ym[20];
        __shared__ float h2s[10];
        if (t < 20) ym[t] = g_mean[t];
        __syncthreads();
        if (t < 10) {
            float a = fcn_b1[t];
            const float* w = fcn_w1 + t * 20;
#pragma unroll
            for (int k = 0; k < 20; k++) a = fmaf(ym[k], w[k], a);
            h2s[t] = 1.f / (1.f + expf(-a));
        }
        __syncthreads();
        if (t == 0) {
            float l0 = fcn_b2[0], l1 = fcn_b2[1];
#pragma unroll
            for (int j = 0; j < 10; j++) {
                l0 = fmaf(h2s[j], fcn_w2[j], l0);
                l1 = fmaf(h2s[j], fcn_w2[10 + j], l1);
            }
            float m = fmaxf(l0, l1);
            float e0 = expf(l0 - m), e1 = expf(l1 - m);
            float inv = 1.f / (e0 + e1);
            out[0] = e0 * inv;
            out[1] = e1 * inv;
        }
    }
}

extern "C" void kernel_launch(void* const* d_in, const int* in_sizes, int n_in,
                              void* d_out, int out_size) {
    const float* x      = (const float*)d_in[0];
    const float* se_w1  = (const float*)d_in[1];
    const float* se_b1  = (const float*)d_in[2];
    const float* se_w2  = (const float*)d_in[3];
    const float* se_b2  = (const float*)d_in[4];
    const float* conv_w = (const float*)d_in[5];
    const float* conv_b = (const float*)d_in[6];
    const float* fcn_w1 = (const float*)d_in[7];
    const float* fcn_b1 = (const float*)d_in[8];
    const float* fcn_w2 = (const float*)d_in[9];
    const float* fcn_b2 = (const float*)d_in[10];

    cnn_fused<<<NB, NT>>>(x, se_w1, se_b1, se_w2, se_b2, conv_w, conv_b,
                          fcn_w1, fcn_b1, fcn_w2, fcn_b2, (float*)d_out);
}

// round 3
// speedup vs baseline: 3.2838x; 1.6064x over previous
#include <cuda_runtime.h>
#include <math.h>

// Scratch (no cudaMalloc allowed)
__device__ float g_sew[128];               // se weights (2 x 64)
__device__ float g_mean[20];               // per-(o,hi) relu-mean
__device__ volatile unsigned g_flag = 0;   // se_w ready flag (self-resetting)
__device__ unsigned g_done = 0;            // combine-block completion counter

#define NB 21
#define NT 256

__device__ __forceinline__ float fast_sigmoid(float a) {
    return 1.f / (1.f + __expf(-a));
}
__device__ __forceinline__ float fast_tanh(float a) {
    float e = __expf(2.f * a);
    return (e - 1.f) / (e + 1.f);
}

__global__ void __launch_bounds__(NT, 1)
cnn_fused(const float* __restrict__ x,
          const float* __restrict__ se_w1,
          const float* __restrict__ se_b1,
          const float* __restrict__ se_w2,
          const float* __restrict__ se_b2,
          const float* __restrict__ conv_w,
          const float* __restrict__ conv_b,
          const float* __restrict__ fcn_w1,
          const float* __restrict__ fcn_b1,
          const float* __restrict__ fcn_w2,
          const float* __restrict__ fcn_b2,
          float* __restrict__ out) {
    const int t = threadIdx.x;
    const int b = blockIdx.x;
    const int lane = t & 31;
    const int wrp = t >> 5;

    if (b == 20) {
        // ================= SE block: compute g_sew, raise flag =================
        __shared__ float norme[64];
        __shared__ float scal[4];
        __shared__ float eegr[128];
        __shared__ float hsh[128];
        __shared__ float ssh[128];

        // Round 1: per-channel norms, 4 threads/channel, shfl reduce.
        {
            int c = t >> 2, k = t & 3;
            const float* e = x + (c + 1) * 128;
            float a = 0.f;
#pragma unroll
            for (int j = 0; j < 32; j++) { float v = e[k + 4 * j]; a = fmaf(v, v, a); }
            a += __shfl_xor_sync(0xffffffffu, a, 1);
            a += __shfl_xor_sync(0xffffffffu, a, 2);
            if (k == 0) norme[c] = sqrtf(a);
        }
        // Round 2: warps 0..3 -> dot0a, dot0b, ||wav_a||, ||wav_b||
        if (wrp < 4) {
            const float* e0 = x + 128;                       // eeg channel 0
            const float* wv = (wrp & 1) ? (x + 65 * 128) : x; // wav_b : wav_a
            float a = 0.f;
            if (wrp < 2) {
#pragma unroll
                for (int j = 0; j < 4; j++) a = fmaf(e0[lane + 32 * j], wv[lane + 32 * j], a);
            } else {
#pragma unroll
                for (int j = 0; j < 4; j++) { float v = wv[lane + 32 * j]; a = fmaf(v, v, a); }
            }
#pragma unroll
            for (int s = 16; s >= 1; s >>= 1) a += __shfl_xor_sync(0xffffffffu, a, s);
            if (lane == 0) scal[wrp] = (wrp < 2) ? a : sqrtf(a);
        }
        __syncthreads();

        // Reference quirk: numerator = channel-0 dot only (jnp.diagonal of (64,1)).
        if (t < 128) {
            int r = t >> 6, j = t & 63;
            eegr[t] = scal[r] / (norme[j] * scal[2 + r]);
        }
        __syncthreads();

        // GEMV1: 128 outputs, 2 threads each (32 FMAs + 1 shfl), tanh.
        {
            int j2 = t >> 1, p = t & 1;
            int r = j2 >> 6, jj = j2 & 63;
            const float* w = se_w1 + jj * 64;
            const float* er = eegr + r * 64;
            float a = 0.f;
#pragma unroll
            for (int m = 0; m < 32; m++) a = fmaf(er[p + 2 * m], w[p + 2 * m], a);
            a += __shfl_xor_sync(0xffffffffu, a, 1);
            if (p == 0) hsh[j2] = fast_tanh(a + se_b1[jj]);
        }
        __syncthreads();

        // GEMV2: same shape, sigmoid.
        {
            int j2 = t >> 1, p = t & 1;
            int r = j2 >> 6, jj = j2 & 63;
            const float* w = se_w2 + jj * 64;
            const float* hr = hsh + r * 64;
            float a = 0.f;
#pragma unroll
            for (int m = 0; m < 32; m++) a = fmaf(hr[p + 2 * m], w[p + 2 * m], a);
            a += __shfl_xor_sync(0xffffffffu, a, 1);
            if (p == 0) ssh[j2] = fast_sigmoid(a + se_b2[jj]);
        }
        __syncthreads();

        // Row-wise softmax over 64: warp 0 -> row 0, warp 1 -> row 1.
        if (wrp < 2) {
            float v0 = ssh[wrp * 64 + lane];
            float v1 = ssh[wrp * 64 + 32 + lane];
            float m = fmaxf(v0, v1);
#pragma unroll
            for (int s = 16; s >= 1; s >>= 1) m = fmaxf(m, __shfl_xor_sync(0xffffffffu, m, s));
            float e0 = __expf(v0 - m), e1 = __expf(v1 - m);
            float su = e0 + e1;
#pragma unroll
            for (int s = 16; s >= 1; s >>= 1) su += __shfl_xor_sync(0xffffffffu, su, s);
            float inv = 1.f / su;
            g_sew[wrp * 64 + lane] = e0 * inv;
            g_sew[wrp * 64 + 32 + lane] = e1 * inv;
        }
        __syncthreads();
        if (t == 0) { __threadfence(); g_flag = 1u; }
        return;
    }

    // ================= Combine blocks: b = o*2 + hi =================
    __shared__ float Tsh[64 * 120];    // 30 KB
    __shared__ float ws[64];
    __shared__ float red[4];
    const int o = b >> 1, hi = b & 1;

    // Stage A: T[kh][wi] = sum_kw eeg[kh][wi+kw] * conv_w[o,kh,kw]
    // thread t -> kh = t>>2, quarter q = t&3 covering 30 wi each.
    {
        int kh = t >> 2, q = t & 3, wi0 = q * 30;
        const float* e = x + (kh + 1) * 128 + wi0;
        const float* w = conv_w + (o * 64 + kh) * 9;
        float wr[9];
#pragma unroll
        for (int i = 0; i < 9; i++) wr[i] = w[i];
        float win[38];
#pragma unroll
        for (int i = 0; i < 38; i++) win[i] = e[i];
        float* Trow = Tsh + kh * 120 + wi0;
#pragma unroll
        for (int j = 0; j < 30; j++) {
            float s = 0.f;
#pragma unroll
            for (int kk = 0; kk < 9; kk++) s = fmaf(win[j + kk], wr[kk], s);
            Trow[j] = s;
        }
    }

    // Wait for se_w (usually already ready by now).
    if (t == 0) {
        while (g_flag == 0u) __nanosleep(32);
        __threadfence();
    }
    __syncthreads();
    if (t < 64) ws[t] = __ldcg(&g_sew[hi * 64 + t]);
    __syncthreads();

    // Stage B: per-wi dot over kh, relu.
    float val = 0.f;
    if (t < 120) {
        const float* Tc = Tsh + t;
        float a0 = 0.f, a1 = 0.f, a2 = 0.f, a3 = 0.f;
#pragma unroll
        for (int kh = 0; kh < 64; kh += 4) {
            a0 = fmaf(ws[kh + 0], Tc[(kh + 0) * 120], a0);
            a1 = fmaf(ws[kh + 1], Tc[(kh + 1) * 120], a1);
            a2 = fmaf(ws[kh + 2], Tc[(kh + 2) * 120], a2);
            a3 = fmaf(ws[kh + 3], Tc[(kh + 3) * 120], a3);
        }
        val = fmaxf(conv_b[o] + ((a0 + a1) + (a2 + a3)), 0.f);
    }
    // Reduce 120 values (warps 0..3; lanes >=120 contribute 0).
#pragma unroll
    for (int s = 16; s >= 1; s >>= 1) val += __shfl_xor_sync(0xffffffffu, val, s);
    if (wrp < 4 && lane == 0) red[wrp] = val;
    __syncthreads();

    if (t == 0) {
        g_mean[b] = (red[0] + red[1] + red[2] + red[3]) * (1.f / 120.f);
        __threadfence();
        unsigned old = atomicAdd(&g_done, 1u);
        if (old == 19u) {
            // Finisher: FCN tail + softmax, then reset sync state for replay.
            __threadfence();
            float ym[20];
#pragma unroll
            for (int k = 0; k < 20; k++) ym[k] = __ldcg(&g_mean[k]);
            float h2[10];
#pragma unroll
            for (int j = 0; j < 10; j++) {
                float a = fcn_b1[j];
                const float* w = fcn_w1 + j * 20;
#pragma unroll
                for (int k = 0; k < 20; k++) a = fmaf(ym[k], w[k], a);
                h2[j] = fast_sigmoid(a);
            }
            float l0 = fcn_b2[0], l1 = fcn_b2[1];
#pragma unroll
            for (int j = 0; j < 10; j++) {
                l0 = fmaf(h2[j], fcn_w2[j], l0);
                l1 = fmaf(h2[j], fcn_w2[10 + j], l1);
            }
            float m = fmaxf(l0, l1);
            float e0 = __expf(l0 - m), e1 = __expf(l1 - m);
            float inv = 1.f / (e0 + e1);
            out[0] = e0 * inv;
            out[1] = e1 * inv;
            // Reset for next graph replay.
            g_done = 0u;
            __threadfence();
            g_flag = 0u;
        }
    }
}

extern "C" void kernel_launch(void* const* d_in, const int* in_sizes, int n_in,
                              void* d_out, int out_size) {
    const float* x      = (const float*)d_in[0];
    const float* se_w1  = (const float*)d_in[1];
    const float* se_b1  = (const float*)d_in[2];
    const float* se_w2  = (const float*)d_in[3];
    const float* se_b2  = (const float*)d_in[4];
    const float* conv_w = (const float*)d_in[5];
    const float* conv_b = (const float*)d_in[6];
    const float* fcn_w1 = (const float*)d_in[7];
    const float* fcn_b1 = (const float*)d_in[8];
    const float* fcn_w2 = (const float*)d_in[9];
    const float* fcn_b2 = (const float*)d_in[10];

    cnn_fused<<<NB, NT>>>(x, se_w1, se_b1, se_w2, se_b2, conv_w, conv_b,
                          fcn_w1, fcn_b1, fcn_w2, fcn_b2, (float*)d_out);
}

// round 4
// speedup vs baseline: 3.6269x; 1.1045x over previous
#include <cuda_runtime.h>
#include <math.h>

// Global scratch (no cudaMalloc allowed)
__device__ float g_mean[20];    // per-(o,hi) relu-mean
__device__ unsigned g_done = 0; // completion counter (self-resetting)

#define NB 10
#define NT 256

__device__ __forceinline__ float fast_sigmoid(float a) {
    return 1.f / (1.f + __expf(-a));
}
__device__ __forceinline__ float fast_tanh(float a) {
    float e = __expf(2.f * a);
    return (e - 1.f) / (e + 1.f);
}
__device__ __forceinline__ void bar_sew() {     // named barrier: sew group = threads 0..127
    asm volatile("bar.sync 1, 128;" ::: "memory");
}

__global__ void __launch_bounds__(NT, 1)
cnn_fused(const float* __restrict__ x,
          const float* __restrict__ se_w1,
          const float* __restrict__ se_b1,
          const float* __restrict__ se_w2,
          const float* __restrict__ se_b2,
          const float* __restrict__ conv_w,
          const float* __restrict__ conv_b,
          const float* __restrict__ fcn_w1,
          const float* __restrict__ fcn_b1,
          const float* __restrict__ fcn_w2,
          const float* __restrict__ fcn_b2,
          float* __restrict__ out) {
    const int t = threadIdx.x;
    const int o = blockIdx.x;
    const int lane = t & 31;
    const int wrp = t >> 5;

    __shared__ float Tsh[64 * 120];  // T[kh][wi], 30 KB
    __shared__ float invn[64];
    __shared__ float scalsh[4];
    __shared__ float crsh[2];
    __shared__ float ush[64];
    __shared__ float hsh[128];
    __shared__ float ssh[128];
    __shared__ float sewsh[128];     // interleaved [kh*2 + hi]
    __shared__ float redsh[16];

    if (t < 128) {
        // ===================== SE path (warps 0-3, named barriers) =====================
        // S1: 68 parallel 128-length reductions.
        if (t < 64) {
            const float4* e = (const float4*)(x + (t + 1) * 128);
            float a0 = 0.f, a1 = 0.f, a2 = 0.f, a3 = 0.f;
#pragma unroll
            for (int i = 0; i < 32; i++) {
                float4 v = e[i];
                a0 = fmaf(v.x, v.x, a0); a1 = fmaf(v.y, v.y, a1);
                a2 = fmaf(v.z, v.z, a2); a3 = fmaf(v.w, v.w, a3);
            }
            invn[t] = rsqrtf((a0 + a1) + (a2 + a3));
        } else if (t < 68) {
            int which = t - 64;
            const float4* e0 = (const float4*)(x + 128);                     // eeg ch 0
            const float4* wv = (const float4*)(x + ((which & 1) ? 65 * 128 : 0));
            float a0 = 0.f, a1 = 0.f, a2 = 0.f, a3 = 0.f;
            if (which < 2) {
#pragma unroll
                for (int i = 0; i < 32; i++) {
                    float4 v = e0[i], w = wv[i];
                    a0 = fmaf(v.x, w.x, a0); a1 = fmaf(v.y, w.y, a1);
                    a2 = fmaf(v.z, w.z, a2); a3 = fmaf(v.w, w.w, a3);
                }
            } else {
#pragma unroll
                for (int i = 0; i < 32; i++) {
                    float4 v = wv[i];
                    a0 = fmaf(v.x, v.x, a0); a1 = fmaf(v.y, v.y, a1);
                    a2 = fmaf(v.z, v.z, a2); a3 = fmaf(v.w, v.w, a3);
                }
            }
            scalsh[which] = (a0 + a1) + (a2 + a3);   // dots raw; norms as sumsq
        }
        bar_sew();

        // S2: u[j] = sum_i w1[j][i] * invn[i]  (r-independent factorization),
        //     plus c_r = dot0_r * rsqrt(sumsq_wav_r).
        {
            int j = t >> 1, p = t & 1;
            const float* w = se_w1 + j * 64;
            float a0 = 0.f, a1 = 0.f;
#pragma unroll
            for (int m = 0; m < 16; m++) {
                a0 = fmaf(w[p + 4 * m],     invn[p + 4 * m],     a0);
                a1 = fmaf(w[p + 2 + 4 * m], invn[p + 2 + 4 * m], a1);
            }
            float a = a0 + a1;
            a += __shfl_xor_sync(0xffffffffu, a, 1);
            if (p == 0) ush[j] = a;
            if (t == 126) crsh[0] = scalsh[0] * rsqrtf(scalsh[2]);
            if (t == 127) crsh[1] = scalsh[1] * rsqrtf(scalsh[3]);
        }
        bar_sew();

        // S3: h[r][j] = tanh(c_r * u[j] + b1[j])
        {
            int r = t >> 6, j = t & 63;
            hsh[t] = fast_tanh(fmaf(crsh[r], ush[j], se_b1[j]));
        }
        bar_sew();

        // S4: GEMV2 + sigmoid
        {
            int r = t >> 6, j = t & 63;
            const float4* w = (const float4*)(se_w2 + j * 64);
            const float* hr = hsh + r * 64;
            float a0 = 0.f, a1 = 0.f, a2 = 0.f, a3 = 0.f;
#pragma unroll
            for (int i = 0; i < 16; i++) {
                float4 v = w[i];
                a0 = fmaf(v.x, hr[4 * i + 0], a0); a1 = fmaf(v.y, hr[4 * i + 1], a1);
                a2 = fmaf(v.z, hr[4 * i + 2], a2); a3 = fmaf(v.w, hr[4 * i + 3], a3);
            }
            ssh[t] = fast_sigmoid(((a0 + a1) + (a2 + a3)) + se_b2[j]);
        }
        bar_sew();

        // S5: row softmax over 64 (warp r handles row r), write interleaved sewsh.
        if (wrp < 2) {
            float v0 = ssh[wrp * 64 + lane];
            float v1 = ssh[wrp * 64 + 32 + lane];
            float m = fmaxf(v0, v1);
#pragma unroll
            for (int s = 16; s >= 1; s >>= 1) m = fmaxf(m, __shfl_xor_sync(0xffffffffu, m, s));
            float e0 = __expf(v0 - m), e1 = __expf(v1 - m);
            float su = e0 + e1;
#pragma unroll
            for (int s = 16; s >= 1; s >>= 1) su += __shfl_xor_sync(0xffffffffu, su, s);
            float inv = 1.f / su;
            sewsh[lane * 2 + wrp] = e0 * inv;
            sewsh[(lane + 32) * 2 + wrp] = e1 * inv;
        }
    } else {
        // ===================== Stage A (warps 4-7): build T into smem =====================
        int ts = t - 128;
        int row = ts >> 1, h = ts & 1, wi0 = h * 60;
        const float4* ep = (const float4*)(x + (row + 1) * 128 + wi0);  // wi0 in {0,60}: 16B-aligned
        float win[68];
#pragma unroll
        for (int i = 0; i < 17; i++) {
            float4 v = ep[i];
            win[4 * i + 0] = v.x; win[4 * i + 1] = v.y;
            win[4 * i + 2] = v.z; win[4 * i + 3] = v.w;
        }
        const float* wp = conv_w + (o * 64 + row) * 9;
        float wr[9];
#pragma unroll
        for (int i = 0; i < 9; i++) wr[i] = wp[i];
        float* Trow = Tsh + row * 120 + wi0;
#pragma unroll
        for (int j = 0; j < 60; j++) {
            float s = 0.f;
#pragma unroll
            for (int k = 0; k < 9; k++) s = fmaf(win[j + k], wr[k], s);
            Trow[j] = s;
        }
    }
    __syncthreads();

    // ===================== Combine: 240 outputs (hi = t&1, wi = t>>1) =====================
    float val = 0.f;
    if (t < 240) {
        int hi = t & 1, wi = t >> 1;
        const float* Tc = Tsh + wi;
        const float* wsp = sewsh + hi;            // [kh*2 + hi]
        float a0 = 0.f, a1 = 0.f, a2 = 0.f, a3 = 0.f;
#pragma unroll
        for (int kh = 0; kh < 64; kh += 4) {
            a0 = fmaf(wsp[2 * (kh + 0)], Tc[(kh + 0) * 120], a0);
            a1 = fmaf(wsp[2 * (kh + 1)], Tc[(kh + 1) * 120], a1);
            a2 = fmaf(wsp[2 * (kh + 2)], Tc[(kh + 2) * 120], a2);
            a3 = fmaf(wsp[2 * (kh + 3)], Tc[(kh + 3) * 120], a3);
        }
        val = fmaxf(conv_b[o] + ((a0 + a1) + (a2 + a3)), 0.f);
    }
    // Parity-preserving reduction: lanes with same bit0 (same hi) sum together.
#pragma unroll
    for (int s = 2; s <= 16; s <<= 1) val += __shfl_xor_sync(0xffffffffu, val, s);
    if (lane < 2) redsh[wrp * 2 + lane] = val;
    __syncthreads();

    if (t == 0) {
        float m0 = 0.f, m1 = 0.f;
#pragma unroll
        for (int w = 0; w < 8; w++) { m0 += redsh[2 * w]; m1 += redsh[2 * w + 1]; }
        g_mean[o * 2 + 0] = m0 * (1.f / 120.f);
        g_mean[o * 2 + 1] = m1 * (1.f / 120.f);
        __threadfence();
        unsigned old = atomicAdd(&g_done, 1u);
        if (old == NB - 1) {
            // Finisher: FCN tail + softmax; reset counter for graph replay.
            __threadfence();
            float ym[20];
#pragma unroll
            for (int k = 0; k < 20; k++) ym[k] = __ldcg(&g_mean[k]);
            float h2[10];
#pragma unroll
            for (int j = 0; j < 10; j++) {
                float a = fcn_b1[j];
                const float* w = fcn_w1 + j * 20;
#pragma unroll
                for (int k = 0; k < 20; k++) a = fmaf(ym[k], w[k], a);
                h2[j] = fast_sigmoid(a);
            }
            float l0 = fcn_b2[0], l1 = fcn_b2[1];
#pragma unroll
            for (int j = 0; j < 10; j++) {
                l0 = fmaf(h2[j], fcn_w2[j], l0);
                l1 = fmaf(h2[j], fcn_w2[10 + j], l1);
            }
            float m = fmaxf(l0, l1);
            float e0 = __expf(l0 - m), e1 = __expf(l1 - m);
            float inv = 1.f / (e0 + e1);
            out[0] = e0 * inv;
            out[1] = e1 * inv;
            g_done = 0u;   // replay-safe reset
        }
    }
}

extern "C" void kernel_launch(void* const* d_in, const int* in_sizes, int n_in,
                              void* d_out, int out_size) {
    const float* x      = (const float*)d_in[0];
    const float* se_w1  = (const float*)d_in[1];
    const float* se_b1  = (const float*)d_in[2];
    const float* se_w2  = (const float*)d_in[3];
    const float* se_b2  = (const float*)d_in[4];
    const float* conv_w = (const float*)d_in[5];
    const float* conv_b = (const float*)d_in[6];
    const float* fcn_w1 = (const float*)d_in[7];
    const float* fcn_b1 = (const float*)d_in[8];
    const float* fcn_w2 = (const float*)d_in[9];
    const float* fcn_b2 = (const float*)d_in[10];

    cnn_fused<<<NB, NT>>>(x, se_w1, se_b1, se_w2, se_b2, conv_w, conv_b,
                          fcn_w1, fcn_b1, fcn_w2, fcn_b2, (float*)d_out);
}